// round 3
// baseline (speedup 1.0000x reference)
#include <cuda_runtime.h>
#include <math.h>

#define DIMM 768
#define NH 12
#define HD 64
#define HIDDEN 3072
#define BATCH 4
#define SEQ 2048
#define TOK (BATCH*SEQ)
#define QKVW (3*DIMM)
#define EPS 1e-6f
#define ATT_SCALE 0.125f   // 64^-0.5

// ---------------- scratch (no cudaMalloc allowed) ----------------
__device__ float g_h[TOK*DIMM];        // LN output (reused for LN1 and LN2)
__device__ float g_qkv[TOK*QKVW];      // qkv projection
__device__ float g_wa[TOK*DIMM];       // attention output
__device__ float g_x1[TOK*DIMM];       // x after attention residual
__device__ float g_hid[TOK*HIDDEN];    // FFN hidden

// ---------------- LayerNorm ----------------
__global__ void ln_kernel(const float* __restrict__ x,
                          const float* __restrict__ gamma,
                          const float* __restrict__ beta,
                          float* __restrict__ out)
{
    int row = blockIdx.x;
    const float* xr = x + (size_t)row * DIMM;
    int t = threadIdx.x;
    float v0 = xr[t], v1 = xr[t + 256], v2 = xr[t + 512];
    float s  = v0 + v1 + v2;
    float sq = v0*v0 + v1*v1 + v2*v2;
    #pragma unroll
    for (int o = 16; o > 0; o >>= 1) {
        s  += __shfl_xor_sync(0xffffffffu, s,  o);
        sq += __shfl_xor_sync(0xffffffffu, sq, o);
    }
    __shared__ float rs[8], rq[8];
    int w = t >> 5, l = t & 31;
    if (l == 0) { rs[w] = s; rq[w] = sq; }
    __syncthreads();
    s = 0.f; sq = 0.f;
    #pragma unroll
    for (int i = 0; i < 8; i++) { s += rs[i]; sq += rq[i]; }
    float mu  = s * (1.0f / DIMM);
    float var = sq * (1.0f / DIMM) - mu * mu;
    float r   = rsqrtf(var + EPS);
    float* orow = out + (size_t)row * DIMM;
    orow[t]       = (v0 - mu) * r * gamma[t]       + beta[t];
    orow[t + 256] = (v1 - mu) * r * gamma[t + 256] + beta[t + 256];
    orow[t + 512] = (v2 - mu) * r * gamma[t + 512] + beta[t + 512];
}

// ---------------- GEMM: C = A[MxK] * B[KxN] + bias (+res / gelu) ----------------
__device__ __forceinline__ float gelu_exact(float x) {
    return 0.5f * x * (1.0f + erff(x * 0.70710678118654752f));
}

// EPI: 0 = bias only, 1 = bias + residual, 2 = bias + gelu
template<int EPI>
__global__ void __launch_bounds__(256)
sgemm_kernel(const float* __restrict__ A, const float* __restrict__ B,
             const float* __restrict__ bias, const float* __restrict__ res,
             float* __restrict__ C, int M, int N, int K)
{
    __shared__ float As[16][128];
    __shared__ float Bs[16][128];

    int tid = threadIdx.x;
    int bm = blockIdx.y, bn = blockIdx.x;
    int tx = tid & 15, ty = tid >> 4;

    float acc[8][8];
    #pragma unroll
    for (int i = 0; i < 8; i++)
        #pragma unroll
        for (int j = 0; j < 8; j++) acc[i][j] = 0.f;

    const float* Ab = A + (size_t)bm * 128 * K;
    const float* Bb = B + (size_t)bn * 128;

    for (int k0 = 0; k0 < K; k0 += 16) {
        #pragma unroll
        for (int lld = 0; lld < 2; lld++) {
            int idx = tid + lld * 256;
            int ar = idx >> 2, ac = (idx & 3) << 2;
            float4 va = *(const float4*)(Ab + (size_t)ar * K + k0 + ac);
            As[ac + 0][ar] = va.x; As[ac + 1][ar] = va.y;
            As[ac + 2][ar] = va.z; As[ac + 3][ar] = va.w;
            int br = idx >> 5, bc = (idx & 31) << 2;
            float4 vb = *(const float4*)(Bb + (size_t)(k0 + br) * N + bc);
            *(float4*)(&Bs[br][bc]) = vb;
        }
        __syncthreads();
        #pragma unroll
        for (int k = 0; k < 16; k++) {
            float a[8], b[8];
            *(float4*)(a)     = *(const float4*)(&As[k][ty * 8]);
            *(float4*)(a + 4) = *(const float4*)(&As[k][ty * 8 + 4]);
            *(float4*)(b)     = *(const float4*)(&Bs[k][tx * 8]);
            *(float4*)(b + 4) = *(const float4*)(&Bs[k][tx * 8 + 4]);
            #pragma unroll
            for (int i = 0; i < 8; i++)
                #pragma unroll
                for (int j = 0; j < 8; j++)
                    acc[i][j] += a[i] * b[j];
        }
        __syncthreads();
    }

    int rowBase = bm * 128 + ty * 8;
    int colBase = bn * 128 + tx * 8;
    float bv[8];
    *(float4*)(bv)     = *(const float4*)(bias + colBase);
    *(float4*)(bv + 4) = *(const float4*)(bias + colBase + 4);
    #pragma unroll
    for (int i = 0; i < 8; i++) {
        float v[8];
        #pragma unroll
        for (int j = 0; j < 8; j++) v[j] = acc[i][j] + bv[j];
        if (EPI == 1) {
            const float* rrow = res + (size_t)(rowBase + i) * N + colBase;
            float rv[8];
            *(float4*)(rv)     = *(const float4*)(rrow);
            *(float4*)(rv + 4) = *(const float4*)(rrow + 4);
            #pragma unroll
            for (int j = 0; j < 8; j++) v[j] += rv[j];
        }
        if (EPI == 2) {
            #pragma unroll
            for (int j = 0; j < 8; j++) v[j] = gelu_exact(v[j]);
        }
        float* crow = C + (size_t)(rowBase + i) * N + colBase;
        *(float4*)(crow)     = *(const float4*)(v);
        *(float4*)(crow + 4) = *(const float4*)(v + 4);
    }
}

// ---------------- Flash attention, fp32, 64x64 tiles ----------------
// grid: (SEQ/64, NH, BATCH), block 256 (16x16 threads, each computing a 4x4 patch)
__global__ void __launch_bounds__(256)
attn_kernel(const float* __restrict__ qkv, const int* __restrict__ mask,
            float* __restrict__ out)
{
    __shared__ float Qs[64][64];   // transposed: [d][q], SCALE folded in
    __shared__ float KP[64][64];   // K transposed [d][k]; reused for P [q][k]
    __shared__ float Vs[64][64];   // [k][d]

    int qb = blockIdx.x, h = blockIdx.y, b = blockIdx.z;
    int tid = threadIdx.x, tx = tid & 15, ty = tid >> 4;

    const float* qbase = qkv + ((size_t)(b * SEQ + qb * 64)) * QKVW + h * HD;

    // load Q tile (transposed write is bank-conflict-free with row = idx%64 mapping)
    #pragma unroll
    for (int lld = 0; lld < 4; lld++) {
        int idx = tid + lld * 256;
        int r = idx & 63, c4 = (idx >> 6) << 2;
        float4 v = *(const float4*)(qbase + (size_t)r * QKVW + c4);
        Qs[c4 + 0][r] = v.x * ATT_SCALE; Qs[c4 + 1][r] = v.y * ATT_SCALE;
        Qs[c4 + 2][r] = v.z * ATT_SCALE; Qs[c4 + 3][r] = v.w * ATT_SCALE;
    }

    float o[4][4];
    float m[4], lsum[4];
    #pragma unroll
    for (int i = 0; i < 4; i++) {
        m[i] = -1e30f; lsum[i] = 0.f;
        #pragma unroll
        for (int j = 0; j < 4; j++) o[i][j] = 0.f;
    }

    const int* maskb = mask + (size_t)b * SEQ * SEQ;
    int qg0 = qb * 64 + ty * 4;

    for (int kb = 0; kb < SEQ / 64; kb++) {
        const float* kbase = qkv + ((size_t)(b * SEQ + kb * 64)) * QKVW + DIMM + h * HD;
        const float* vbase = kbase + DIMM;
        __syncthreads();   // prev PV done before overwriting KP/Vs (covers Q load too)
        #pragma unroll
        for (int lld = 0; lld < 4; lld++) {
            int idx = tid + lld * 256;
            int r = idx & 63, c4 = (idx >> 6) << 2;
            float4 v = *(const float4*)(kbase + (size_t)r * QKVW + c4);
            KP[c4 + 0][r] = v.x; KP[c4 + 1][r] = v.y;
            KP[c4 + 2][r] = v.z; KP[c4 + 3][r] = v.w;
            int vr = idx >> 4, vc = (idx & 15) << 2;
            float4 vv = *(const float4*)(vbase + (size_t)vr * QKVW + vc);
            *(float4*)(&Vs[vr][vc]) = vv;
        }
        __syncthreads();

        // scores S = (SCALE*Q) K^T, 4x4 per thread
        float s[4][4];
        #pragma unroll
        for (int i = 0; i < 4; i++)
            #pragma unroll
            for (int j = 0; j < 4; j++) s[i][j] = 0.f;
        #pragma unroll
        for (int d = 0; d < 64; d++) {
            float a[4], bk[4];
            *(float4*)a  = *(const float4*)(&Qs[d][ty * 4]);
            *(float4*)bk = *(const float4*)(&KP[d][tx * 4]);
            #pragma unroll
            for (int i = 0; i < 4; i++)
                #pragma unroll
                for (int j = 0; j < 4; j++)
                    s[i][j] += a[i] * bk[j];
        }

        // mask + online softmax (row group = 16 lanes sharing ty)
        int kg0 = kb * 64 + tx * 4;
        #pragma unroll
        for (int i = 0; i < 4; i++) {
            const int* mrow = maskb + (size_t)(qg0 + i) * SEQ + kg0;
            int4 mv = *(const int4*)mrow;
            if (mv.x == 0) s[i][0] = -10000.f;
            if (mv.y == 0) s[i][1] = -10000.f;
            if (mv.z == 0) s[i][2] = -10000.f;
            if (mv.w == 0) s[i][3] = -10000.f;
            float rmax = fmaxf(fmaxf(s[i][0], s[i][1]), fmaxf(s[i][2], s[i][3]));
            #pragma unroll
            for (int off = 8; off > 0; off >>= 1)
                rmax = fmaxf(rmax, __shfl_xor_sync(0xffffffffu, rmax, off));
            float mn = fmaxf(m[i], rmax);
            float corr = __expf(m[i] - mn);
            m[i] = mn;
            float rs = 0.f;
            #pragma unroll
            for (int j = 0; j < 4; j++) {
                s[i][j] = __expf(s[i][j] - mn);
                rs += s[i][j];
            }
            #pragma unroll
            for (int off = 8; off > 0; off >>= 1)
                rs += __shfl_xor_sync(0xffffffffu, rs, off);
            lsum[i] = lsum[i] * corr + rs;
            #pragma unroll
            for (int j = 0; j < 4; j++) o[i][j] *= corr;
        }

        __syncthreads();   // all Ks reads done before P overwrites KP
        #pragma unroll
        for (int i = 0; i < 4; i++)
            *(float4*)(&KP[ty * 4 + i][tx * 4]) =
                make_float4(s[i][0], s[i][1], s[i][2], s[i][3]);
        __syncthreads();

        // O += P @ V
        #pragma unroll
        for (int k4 = 0; k4 < 16; k4++) {
            float p[4][4];
            #pragma unroll
            for (int i = 0; i < 4; i++)
                *(float4*)(p[i]) = *(const float4*)(&KP[ty * 4 + i][k4 * 4]);
            #pragma unroll
            for (int kk = 0; kk < 4; kk++) {
                float4 v = *(const float4*)(&Vs[k4 * 4 + kk][tx * 4]);
                #pragma unroll
                for (int i = 0; i < 4; i++) {
                    o[i][0] += p[i][kk] * v.x;
                    o[i][1] += p[i][kk] * v.y;
                    o[i][2] += p[i][kk] * v.z;
                    o[i][3] += p[i][kk] * v.w;
                }
            }
        }
    }

    float* ob = out + ((size_t)(b * SEQ + qb * 64)) * DIMM + h * HD;
    #pragma unroll
    for (int i = 0; i < 4; i++) {
        float inv = 1.0f / lsum[i];
        *(float4*)(&ob[(size_t)(ty * 4 + i) * DIMM + tx * 4]) =
            make_float4(o[i][0] * inv, o[i][1] * inv, o[i][2] * inv, o[i][3] * inv);
    }
}

// ---------------- launch ----------------
extern "C" void kernel_launch(void* const* d_in, const int* in_sizes, int n_in,
                              void* d_out, int out_size)
{
    const float* x      = (const float*)d_in[0];
    const int*   mask   = (const int*)  d_in[1];
    const float* w_qkv  = (const float*)d_in[2];
    const float* b_qkv  = (const float*)d_in[3];
    const float* w_proj = (const float*)d_in[4];
    const float* b_proj = (const float*)d_in[5];
    const float* g1     = (const float*)d_in[6];
    const float* beta1  = (const float*)d_in[7];
    const float* g2     = (const float*)d_in[8];
    const float* beta2  = (const float*)d_in[9];
    const float* w1     = (const float*)d_in[10];
    const float* b1     = (const float*)d_in[11];
    const float* w2     = (const float*)d_in[12];
    const float* b2     = (const float*)d_in[13];
    float* out = (float*)d_out;

    float *p_h, *p_qkv, *p_wa, *p_x1, *p_hid;
    cudaGetSymbolAddress((void**)&p_h,   g_h);
    cudaGetSymbolAddress((void**)&p_qkv, g_qkv);
    cudaGetSymbolAddress((void**)&p_wa,  g_wa);
    cudaGetSymbolAddress((void**)&p_x1,  g_x1);
    cudaGetSymbolAddress((void**)&p_hid, g_hid);

    // LN1
    ln_kernel<<<TOK, 256>>>(x, g1, beta1, p_h);
    // qkv = h @ w_qkv + b_qkv           [8192,768] x [768,2304]
    sgemm_kernel<0><<<dim3(QKVW / 128, TOK / 128), 256>>>(
        p_h, w_qkv, b_qkv, nullptr, p_qkv, TOK, QKVW, DIMM);
    // attention
    attn_kernel<<<dim3(SEQ / 64, NH, BATCH), 256>>>(p_qkv, mask, p_wa);
    // x1 = x + wa @ w_proj + b_proj     [8192,768] x [768,768]
    sgemm_kernel<1><<<dim3(DIMM / 128, TOK / 128), 256>>>(
        p_wa, w_proj, b_proj, x, p_x1, TOK, DIMM, DIMM);
    // LN2
    ln_kernel<<<TOK, 256>>>(p_x1, g2, beta2, p_h);
    // hid = gelu(h @ w1 + b1)           [8192,768] x [768,3072]
    sgemm_kernel<2><<<dim3(HIDDEN / 128, TOK / 128), 256>>>(
        p_h, w1, b1, nullptr, p_hid, TOK, HIDDEN, DIMM);
    // out = x1 + hid @ w2 + b2          [8192,3072] x [3072,768]
    sgemm_kernel<1><<<dim3(DIMM / 128, TOK / 128), 256>>>(
        p_hid, w2, b2, p_x1, out, TOK, DIMM, HIDDEN);
}

// round 8
// speedup vs baseline: 1.6815x; 1.6815x over previous
#include <cuda_runtime.h>
#include <math.h>
#include <stdint.h>

#define DIMM 768
#define NH 12
#define HD 64
#define HIDDEN 3072
#define BATCH 4
#define SEQ 2048
#define TOK (BATCH*SEQ)
#define QKVW (3*DIMM)
#define EPS 1e-6f
#define ATT_SCALE 0.125f   // 64^-0.5

// ---------------- scratch (no cudaMalloc allowed) ----------------
__device__ float g_h[TOK*DIMM];        // LN output (reused for LN1 and LN2)
__device__ float g_qkv[TOK*QKVW];      // qkv projection
__device__ float g_wa[TOK*DIMM];       // attention output
__device__ float g_x1[TOK*DIMM];       // x after attention residual
__device__ float g_hid[TOK*HIDDEN];    // FFN hidden

__device__ __forceinline__ uint32_t f2tf32(float x) {
    uint32_t u;
    asm("cvt.rna.tf32.f32 %0, %1;" : "=r"(u) : "f"(x));
    return u;
}

// ---------------- LayerNorm ----------------
__global__ void ln_kernel(const float* __restrict__ x,
                          const float* __restrict__ gamma,
                          const float* __restrict__ beta,
                          float* __restrict__ out)
{
    int row = blockIdx.x;
    const float* xr = x + (size_t)row * DIMM;
    int t = threadIdx.x;
    float v0 = xr[t], v1 = xr[t + 256], v2 = xr[t + 512];
    float s  = v0 + v1 + v2;
    float sq = v0*v0 + v1*v1 + v2*v2;
    #pragma unroll
    for (int o = 16; o > 0; o >>= 1) {
        s  += __shfl_xor_sync(0xffffffffu, s,  o);
        sq += __shfl_xor_sync(0xffffffffu, sq, o);
    }
    __shared__ float rs[8], rq[8];
    int w = t >> 5, l = t & 31;
    if (l == 0) { rs[w] = s; rq[w] = sq; }
    __syncthreads();
    s = 0.f; sq = 0.f;
    #pragma unroll
    for (int i = 0; i < 8; i++) { s += rs[i]; sq += rq[i]; }
    float mu  = s * (1.0f / DIMM);
    float var = sq * (1.0f / DIMM) - mu * mu;
    float r   = rsqrtf(var + EPS);
    float* orow = out + (size_t)row * DIMM;
    orow[t]       = (v0 - mu) * r * gamma[t]       + beta[t];
    orow[t + 256] = (v1 - mu) * r * gamma[t + 256] + beta[t + 256];
    orow[t + 512] = (v2 - mu) * r * gamma[t + 512] + beta[t + 512];
}

__device__ __forceinline__ float gelu_exact(float x) {
    return 0.5f * x * (1.0f + erff(x * 0.70710678118654752f));
}

// =================== TF32 mma.sync GEMM ===================
// C[M,N] = A[M,K] @ B[K,N] + bias (+res / gelu)
// 128x128 CTA tile, 8 warps (2m x 4n), warp tile 64x32 (4 m16-tiles x 4 n8-tiles),
// K chunked by 32 (4 k-steps of 8), double-buffered fragment-ordered SMEM.
//
// SMEM holds mma fragments directly:
//  A frag (m16k8) = 128 floats: word = lane*4 + reg, frag stride AW=132 (pad 4)
//    element (r,c): lane = ((r&7)<<2)|(c&3), reg = ((r>>3)&1)|(((c>>2)&1)<<1)
//  B frag (k8n8) = 64 floats: word = lane*2 + reg, frag stride BW=68
//    element (k,n): lane = ((n&7)<<2)|(k&3), reg = (k>>2)&1
//  fA = mtile*4 + kstep   (32 frags), fB = kstep*16 + ntile (64 frags)

#define AW 132
#define BW 68
#define ABUF_W (32*AW)               // 4224 words
#define BBUF_W (64*BW)               // 4352 words
#define BUF_W  (ABUF_W + BBUF_W)     // 8576 words
#define GSMEM_BYTES (2*BUF_W*4)      // 68608 bytes

__device__ __forceinline__ void mma_tf32(float* d, const uint32_t* a, const uint32_t* b) {
    asm volatile(
        "mma.sync.aligned.m16n8k8.row.col.f32.tf32.tf32.f32 "
        "{%0,%1,%2,%3}, {%4,%5,%6,%7}, {%8,%9}, {%0,%1,%2,%3};"
        : "+f"(d[0]), "+f"(d[1]), "+f"(d[2]), "+f"(d[3])
        : "r"(a[0]), "r"(a[1]), "r"(a[2]), "r"(a[3]), "r"(b[0]), "r"(b[1]));
}

// epi: 0 = bias, 1 = bias+res, 2 = bias+gelu
__global__ void __launch_bounds__(256)
tgemm_kernel(const float* __restrict__ A, const float* __restrict__ Bw,
             const float* __restrict__ bias, const float* __restrict__ res,
             float* __restrict__ C, int K, int N, int epi)
{
    extern __shared__ float smem[];
    int tid = threadIdx.x;
    int bm = blockIdx.y, bn = blockIdx.x;
    int w = tid >> 5, lane = tid & 31;
    int wm = w >> 2, wn = w & 3;

    float acc[4][4][4];
    #pragma unroll
    for (int i = 0; i < 4; i++)
        #pragma unroll
        for (int j = 0; j < 4; j++)
            #pragma unroll
            for (int r = 0; r < 4; r++) acc[i][j][r] = 0.f;

    const float* Ab = A + (size_t)bm * 128 * K;
    const float* Bb = Bw + bn * 128;

    float4 av[4], bv[4];

    // ---- global load of chunk k0 into regs ----
    auto loadg = [&](int k0) {
        #pragma unroll
        for (int i = 0; i < 4; i++) {
            int idx = tid + i * 256;            // A: r=idx>>3 (0..127), k4=idx&7
            av[i] = *(const float4*)(Ab + (size_t)(idx >> 3) * K + k0 + ((idx & 7) << 2));
        }
        #pragma unroll
        for (int i = 0; i < 4; i++) {
            int idx = tid + i * 256;            // B: kk=idx>>5 (0..31), n4=idx&31
            bv[i] = *(const float4*)(Bb + (size_t)(k0 + (idx >> 5)) * N + ((idx & 31) << 2));
        }
    };

    // ---- store staged regs into fragment-ordered smem buffer ----
    auto stores = [&](float* buf) {
        float* sAd = buf;
        float* sBd = buf + ABUF_W;
        #pragma unroll
        for (int i = 0; i < 4; i++) {
            int idx = tid + i * 256;
            int r = idx >> 3, k4 = idx & 7;
            int fA  = ((r >> 4) << 2) + (k4 >> 1);
            int reg = ((r >> 3) & 1) | ((k4 & 1) << 1);
            float* p = sAd + fA * AW + ((r & 7) << 4) + reg;   // lanebase*4 = (r&7)*16
            p[0]  = __uint_as_float(f2tf32(av[i].x));
            p[4]  = __uint_as_float(f2tf32(av[i].y));
            p[8]  = __uint_as_float(f2tf32(av[i].z));
            p[12] = __uint_as_float(f2tf32(av[i].w));
        }
        #pragma unroll
        for (int i = 0; i < 4; i++) {
            int idx = tid + i * 256;
            int kk = idx >> 5, n4 = idx & 31;
            int fB  = ((kk >> 3) << 4) + (n4 >> 1);
            int reg = (kk >> 2) & 1;
            int lane0 = ((n4 & 1) << 4) | (kk & 3);            // lane for j=0
            float* p = sBd + fB * BW + lane0 * 2 + reg;
            p[0]  = __uint_as_float(f2tf32(bv[i].x));
            p[8]  = __uint_as_float(f2tf32(bv[i].y));
            p[16] = __uint_as_float(f2tf32(bv[i].z));
            p[24] = __uint_as_float(f2tf32(bv[i].w));
        }
    };

    int nch = K >> 5;

    loadg(0);
    stores(smem);
    __syncthreads();

    for (int c = 0; c < nch; c++) {
        int cur = c & 1;
        if (c + 1 < nch) loadg((c + 1) << 5);

        const float* sA = smem + cur * BUF_W;
        const float* sB = sA + ABUF_W;

        #pragma unroll
        for (int ks = 0; ks < 4; ks++) {
            uint32_t afr[4][4], bfr[4][2];
            #pragma unroll
            for (int i = 0; i < 4; i++) {
                float4 va = *(const float4*)(sA + (((wm << 2) + i) * 4 + ks) * AW + (lane << 2));
                afr[i][0] = __float_as_uint(va.x); afr[i][1] = __float_as_uint(va.y);
                afr[i][2] = __float_as_uint(va.z); afr[i][3] = __float_as_uint(va.w);
            }
            #pragma unroll
            for (int j = 0; j < 4; j++) {
                float2 vb = *(const float2*)(sB + ((ks << 4) + (wn << 2) + j) * BW + (lane << 1));
                bfr[j][0] = __float_as_uint(vb.x); bfr[j][1] = __float_as_uint(vb.y);
            }
            #pragma unroll
            for (int i = 0; i < 4; i++)
                #pragma unroll
                for (int j = 0; j < 4; j++)
                    mma_tf32(acc[i][j], afr[i], bfr[j]);
        }

        if (c + 1 < nch) stores(smem + (cur ^ 1) * BUF_W);
        __syncthreads();
    }

    // ---- epilogue ----
    int g = lane >> 2, t = lane & 3;
    int m0 = bm * 128 + wm * 64;
    int n0 = bn * 128 + wn * 32;
    #pragma unroll
    for (int i = 0; i < 4; i++) {
        int row0 = m0 + i * 16 + g;
        #pragma unroll
        for (int j = 0; j < 4; j++) {
            int col = n0 + j * 8 + t * 2;
            float2 bb = *(const float2*)(bias + col);
            float2 v0, v1;
            v0.x = acc[i][j][0] + bb.x; v0.y = acc[i][j][1] + bb.y;
            v1.x = acc[i][j][2] + bb.x; v1.y = acc[i][j][3] + bb.y;
            if (epi == 1) {
                float2 r0 = *(const float2*)(res + (size_t)row0 * N + col);
                float2 r1 = *(const float2*)(res + (size_t)(row0 + 8) * N + col);
                v0.x += r0.x; v0.y += r0.y;
                v1.x += r1.x; v1.y += r1.y;
            } else if (epi == 2) {
                v0.x = gelu_exact(v0.x); v0.y = gelu_exact(v0.y);
                v1.x = gelu_exact(v1.x); v1.y = gelu_exact(v1.y);
            }
            *(float2*)(C + (size_t)row0 * N + col)       = v0;
            *(float2*)(C + (size_t)(row0 + 8) * N + col) = v1;
        }
    }
}

// ---------------- Flash attention, fp32, 64x64 tiles ----------------
__global__ void __launch_bounds__(256)
attn_kernel(const float* __restrict__ qkv, const int* __restrict__ mask,
            float* __restrict__ out)
{
    __shared__ float Qs[64][64];   // transposed: [d][q], SCALE folded in
    __shared__ float KP[64][64];   // K transposed [d][k]; reused for P [q][k]
    __shared__ float Vs[64][64];   // [k][d]

    int qb = blockIdx.x, h = blockIdx.y, b = blockIdx.z;
    int tid = threadIdx.x, tx = tid & 15, ty = tid >> 4;

    const float* qbase = qkv + ((size_t)(b * SEQ + qb * 64)) * QKVW + h * HD;

    #pragma unroll
    for (int lld = 0; lld < 4; lld++) {
        int idx = tid + lld * 256;
        int r = idx & 63, c4 = (idx >> 6) << 2;
        float4 v = *(const float4*)(qbase + (size_t)r * QKVW + c4);
        Qs[c4 + 0][r] = v.x * ATT_SCALE; Qs[c4 + 1][r] = v.y * ATT_SCALE;
        Qs[c4 + 2][r] = v.z * ATT_SCALE; Qs[c4 + 3][r] = v.w * ATT_SCALE;
    }

    float o[4][4];
    float m[4], lsum[4];
    #pragma unroll
    for (int i = 0; i < 4; i++) {
        m[i] = -1e30f; lsum[i] = 0.f;
        #pragma unroll
        for (int j = 0; j < 4; j++) o[i][j] = 0.f;
    }

    const int* maskb = mask + (size_t)b * SEQ * SEQ;
    int qg0 = qb * 64 + ty * 4;

    for (int kb = 0; kb < SEQ / 64; kb++) {
        const float* kbase = qkv + ((size_t)(b * SEQ + kb * 64)) * QKVW + DIMM + h * HD;
        const float* vbase = kbase + DIMM;
        __syncthreads();
        #pragma unroll
        for (int lld = 0; lld < 4; lld++) {
            int idx = tid + lld * 256;
            int r = idx & 63, c4 = (idx >> 6) << 2;
            float4 v = *(const float4*)(kbase + (size_t)r * QKVW + c4);
            KP[c4 + 0][r] = v.x; KP[c4 + 1][r] = v.y;
            KP[c4 + 2][r] = v.z; KP[c4 + 3][r] = v.w;
            int vr = idx >> 4, vc = (idx & 15) << 2;
            float4 vv = *(const float4*)(vbase + (size_t)vr * QKVW + vc);
            *(float4*)(&Vs[vr][vc]) = vv;
        }
        __syncthreads();

        float s[4][4];
        #pragma unroll
        for (int i = 0; i < 4; i++)
            #pragma unroll
            for (int j = 0; j < 4; j++) s[i][j] = 0.f;
        #pragma unroll
        for (int d = 0; d < 64; d++) {
            float a[4], bk[4];
            *(float4*)a  = *(const float4*)(&Qs[d][ty * 4]);
            *(float4*)bk = *(const float4*)(&KP[d][tx * 4]);
            #pragma unroll
            for (int i = 0; i < 4; i++)
                #pragma unroll
                for (int j = 0; j < 4; j++)
                    s[i][j] += a[i] * bk[j];
        }

        int kg0 = kb * 64 + tx * 4;
        #pragma unroll
        for (int i = 0; i < 4; i++) {
            const int* mrow = maskb + (size_t)(qg0 + i) * SEQ + kg0;
            int4 mv = *(const int4*)mrow;
            if (mv.x == 0) s[i][0] = -10000.f;
            if (mv.y == 0) s[i][1] = -10000.f;
            if (mv.z == 0) s[i][2] = -10000.f;
            if (mv.w == 0) s[i][3] = -10000.f;
            float rmax = fmaxf(fmaxf(s[i][0], s[i][1]), fmaxf(s[i][2], s[i][3]));
            #pragma unroll
            for (int off = 8; off > 0; off >>= 1)
                rmax = fmaxf(rmax, __shfl_xor_sync(0xffffffffu, rmax, off));
            float mn = fmaxf(m[i], rmax);
            float corr = __expf(m[i] - mn);
            m[i] = mn;
            float rsum = 0.f;
            #pragma unroll
            for (int j = 0; j < 4; j++) {
                s[i][j] = __expf(s[i][j] - mn);
                rsum += s[i][j];
            }
            #pragma unroll
            for (int off = 8; off > 0; off >>= 1)
                rsum += __shfl_xor_sync(0xffffffffu, rsum, off);
            lsum[i] = lsum[i] * corr + rsum;
            #pragma unroll
            for (int j = 0; j < 4; j++) o[i][j] *= corr;
        }

        __syncthreads();
        #pragma unroll
        for (int i = 0; i < 4; i++)
            *(float4*)(&KP[ty * 4 + i][tx * 4]) =
                make_float4(s[i][0], s[i][1], s[i][2], s[i][3]);
        __syncthreads();

        #pragma unroll
        for (int k4 = 0; k4 < 16; k4++) {
            float p[4][4];
            #pragma unroll
            for (int i = 0; i < 4; i++)
                *(float4*)(p[i]) = *(const float4*)(&KP[ty * 4 + i][k4 * 4]);
            #pragma unroll
            for (int kk = 0; kk < 4; kk++) {
                float4 v = *(const float4*)(&Vs[k4 * 4 + kk][tx * 4]);
                #pragma unroll
                for (int i = 0; i < 4; i++) {
                    o[i][0] += p[i][kk] * v.x;
                    o[i][1] += p[i][kk] * v.y;
                    o[i][2] += p[i][kk] * v.z;
                    o[i][3] += p[i][kk] * v.w;
                }
            }
        }
    }

    float* ob = out + ((size_t)(b * SEQ + qb * 64)) * DIMM + h * HD;
    #pragma unroll
    for (int i = 0; i < 4; i++) {
        float inv = 1.0f / lsum[i];
        *(float4*)(&ob[(size_t)(ty * 4 + i) * DIMM + tx * 4]) =
            make_float4(o[i][0] * inv, o[i][1] * inv, o[i][2] * inv, o[i][3] * inv);
    }
}

// ---------------- launch ----------------
extern "C" void kernel_launch(void* const* d_in, const int* in_sizes, int n_in,
                              void* d_out, int out_size)
{
    const float* x      = (const float*)d_in[0];
    const int*   mask   = (const int*)  d_in[1];
    const float* w_qkv  = (const float*)d_in[2];
    const float* b_qkv  = (const float*)d_in[3];
    const float* w_proj = (const float*)d_in[4];
    const float* b_proj = (const float*)d_in[5];
    const float* g1     = (const float*)d_in[6];
    const float* beta1  = (const float*)d_in[7];
    const float* g2     = (const float*)d_in[8];
    const float* beta2  = (const float*)d_in[9];
    const float* w1     = (const float*)d_in[10];
    const float* b1     = (const float*)d_in[11];
    const float* w2     = (const float*)d_in[12];
    const float* b2     = (const float*)d_in[13];
    float* out = (float*)d_out;

    float *p_h, *p_qkv, *p_wa, *p_x1, *p_hid;
    cudaGetSymbolAddress((void**)&p_h,   g_h);
    cudaGetSymbolAddress((void**)&p_qkv, g_qkv);
    cudaGetSymbolAddress((void**)&p_wa,  g_wa);
    cudaGetSymbolAddress((void**)&p_x1,  g_x1);
    cudaGetSymbolAddress((void**)&p_hid, g_hid);

    cudaFuncSetAttribute(tgemm_kernel,
                         cudaFuncAttributeMaxDynamicSharedMemorySize, GSMEM_BYTES);

    // LN1
    ln_kernel<<<TOK, 256>>>(x, g1, beta1, p_h);
    // qkv = h @ w_qkv + b_qkv           [8192,768] x [768,2304]
    tgemm_kernel<<<dim3(QKVW / 128, TOK / 128), 256, GSMEM_BYTES>>>(
        p_h, w_qkv, b_qkv, nullptr, p_qkv, DIMM, QKVW, 0);
    // attention
    attn_kernel<<<dim3(SEQ / 64, NH, BATCH), 256>>>(p_qkv, mask, p_wa);
    // x1 = x + wa @ w_proj + b_proj     [8192,768] x [768,768]
    tgemm_kernel<<<dim3(DIMM / 128, TOK / 128), 256, GSMEM_BYTES>>>(
        p_wa, w_proj, b_proj, x, p_x1, DIMM, DIMM, 1);
    // LN2
    ln_kernel<<<TOK, 256>>>(p_x1, g2, beta2, p_h);
    // hid = gelu(h @ w1 + b1)           [8192,768] x [768,3072]
    tgemm_kernel<<<dim3(HIDDEN / 128, TOK / 128), 256, GSMEM_BYTES>>>(
        p_h, w1, b1, nullptr, p_hid, DIMM, HIDDEN, 2);
    // out = x1 + hid @ w2 + b2          [8192,3072] x [3072,768]
    tgemm_kernel<<<dim3(DIMM / 128, TOK / 128), 256, GSMEM_BYTES>>>(
        p_hid, w2, b2, p_x1, out, HIDDEN, DIMM, 1);
}

// round 13
// speedup vs baseline: 2.5192x; 1.4981x over previous
#include <cuda_runtime.h>
#include <math.h>
#include <stdint.h>

#define DIMM 768
#define NH 12
#define HD 64
#define HIDDEN 3072
#define BATCH 4
#define SEQ 2048
#define TOK (BATCH*SEQ)
#define QKVW (3*DIMM)
#define EPS 1e-6f
#define ATT_SCALE 0.125f   // 64^-0.5

// ---------------- scratch (no cudaMalloc allowed) ----------------
__device__ float g_h[TOK*DIMM];        // LN output (reused for LN1 and LN2)
__device__ float g_qkv[TOK*QKVW];      // qkv projection
__device__ float g_wa[TOK*DIMM];       // attention output
__device__ float g_x1[TOK*DIMM];       // x after attention residual
__device__ float g_hid[TOK*HIDDEN];    // FFN hidden

__device__ __forceinline__ uint32_t f2tf32(float x) {
    uint32_t u;
    asm("cvt.rna.tf32.f32 %0, %1;" : "=r"(u) : "f"(x));
    return u;
}
__device__ __forceinline__ float tfv(float x) {
    return __uint_as_float(f2tf32(x));
}

// ---------------- LayerNorm ----------------
__global__ void ln_kernel(const float* __restrict__ x,
                          const float* __restrict__ gamma,
                          const float* __restrict__ beta,
                          float* __restrict__ out)
{
    int row = blockIdx.x;
    const float* xr = x + (size_t)row * DIMM;
    int t = threadIdx.x;
    float v0 = xr[t], v1 = xr[t + 256], v2 = xr[t + 512];
    float s  = v0 + v1 + v2;
    float sq = v0*v0 + v1*v1 + v2*v2;
    #pragma unroll
    for (int o = 16; o > 0; o >>= 1) {
        s  += __shfl_xor_sync(0xffffffffu, s,  o);
        sq += __shfl_xor_sync(0xffffffffu, sq, o);
    }
    __shared__ float rs[8], rq[8];
    int w = t >> 5, l = t & 31;
    if (l == 0) { rs[w] = s; rq[w] = sq; }
    __syncthreads();
    s = 0.f; sq = 0.f;
    #pragma unroll
    for (int i = 0; i < 8; i++) { s += rs[i]; sq += rq[i]; }
    float mu  = s * (1.0f / DIMM);
    float var = sq * (1.0f / DIMM) - mu * mu;
    float r   = rsqrtf(var + EPS);
    float* orow = out + (size_t)row * DIMM;
    orow[t]       = (v0 - mu) * r * gamma[t]       + beta[t];
    orow[t + 256] = (v1 - mu) * r * gamma[t + 256] + beta[t + 256];
    orow[t + 512] = (v2 - mu) * r * gamma[t + 512] + beta[t + 512];
}

__device__ __forceinline__ float gelu_exact(float x) {
    return 0.5f * x * (1.0f + erff(x * 0.70710678118654752f));
}

__device__ __forceinline__ void mma_tf32(float* d, const uint32_t* a, const uint32_t* b) {
    asm volatile(
        "mma.sync.aligned.m16n8k8.row.col.f32.tf32.tf32.f32 "
        "{%0,%1,%2,%3}, {%4,%5,%6,%7}, {%8,%9}, {%0,%1,%2,%3};"
        : "+f"(d[0]), "+f"(d[1]), "+f"(d[2]), "+f"(d[3])
        : "r"(a[0]), "r"(a[1]), "r"(a[2]), "r"(a[3]), "r"(b[0]), "r"(b[1]));
}

// =================== TF32 mma.sync GEMM ===================
#define AW 132
#define BW 68
#define ABUF_W (32*AW)
#define BBUF_W (64*BW)
#define BUF_W  (ABUF_W + BBUF_W)
#define GSMEM_BYTES (2*BUF_W*4)

// epi: 0 = bias, 1 = bias+res, 2 = bias+gelu
__global__ void __launch_bounds__(256)
tgemm_kernel(const float* __restrict__ A, const float* __restrict__ Bw,
             const float* __restrict__ bias, const float* __restrict__ res,
             float* __restrict__ C, int K, int N, int epi)
{
    extern __shared__ float smem[];
    int tid = threadIdx.x;
    int bm = blockIdx.y, bn = blockIdx.x;
    int w = tid >> 5, lane = tid & 31;
    int wm = w >> 2, wn = w & 3;

    float acc[4][4][4];
    #pragma unroll
    for (int i = 0; i < 4; i++)
        #pragma unroll
        for (int j = 0; j < 4; j++)
            #pragma unroll
            for (int r = 0; r < 4; r++) acc[i][j][r] = 0.f;

    const float* Ab = A + (size_t)bm * 128 * K;
    const float* Bb = Bw + bn * 128;

    float4 av[4], bv[4];

    auto loadg = [&](int k0) {
        #pragma unroll
        for (int i = 0; i < 4; i++) {
            int idx = tid + i * 256;
            av[i] = *(const float4*)(Ab + (size_t)(idx >> 3) * K + k0 + ((idx & 7) << 2));
        }
        #pragma unroll
        for (int i = 0; i < 4; i++) {
            int idx = tid + i * 256;
            bv[i] = *(const float4*)(Bb + (size_t)(k0 + (idx >> 5)) * N + ((idx & 31) << 2));
        }
    };

    auto stores = [&](float* buf) {
        float* sAd = buf;
        float* sBd = buf + ABUF_W;
        #pragma unroll
        for (int i = 0; i < 4; i++) {
            int idx = tid + i * 256;
            int r = idx >> 3, k4 = idx & 7;
            int fA  = ((r >> 4) << 2) + (k4 >> 1);
            int reg = ((r >> 3) & 1) | ((k4 & 1) << 1);
            float* p = sAd + fA * AW + ((r & 7) << 4) + reg;
            p[0]  = tfv(av[i].x);
            p[4]  = tfv(av[i].y);
            p[8]  = tfv(av[i].z);
            p[12] = tfv(av[i].w);
        }
        #pragma unroll
        for (int i = 0; i < 4; i++) {
            int idx = tid + i * 256;
            int kk = idx >> 5, n4 = idx & 31;
            int fB  = ((kk >> 3) << 4) + (n4 >> 1);
            int reg = (kk >> 2) & 1;
            int lane0 = ((n4 & 1) << 4) | (kk & 3);
            float* p = sBd + fB * BW + lane0 * 2 + reg;
            p[0]  = tfv(bv[i].x);
            p[8]  = tfv(bv[i].y);
            p[16] = tfv(bv[i].z);
            p[24] = tfv(bv[i].w);
        }
    };

    int nch = K >> 5;

    loadg(0);
    stores(smem);
    __syncthreads();

    for (int c = 0; c < nch; c++) {
        int cur = c & 1;
        if (c + 1 < nch) loadg((c + 1) << 5);

        const float* sA = smem + cur * BUF_W;
        const float* sB = sA + ABUF_W;

        #pragma unroll
        for (int ks = 0; ks < 4; ks++) {
            uint32_t afr[4][4], bfr[4][2];
            #pragma unroll
            for (int i = 0; i < 4; i++) {
                float4 va = *(const float4*)(sA + (((wm << 2) + i) * 4 + ks) * AW + (lane << 2));
                afr[i][0] = __float_as_uint(va.x); afr[i][1] = __float_as_uint(va.y);
                afr[i][2] = __float_as_uint(va.z); afr[i][3] = __float_as_uint(va.w);
            }
            #pragma unroll
            for (int j = 0; j < 4; j++) {
                float2 vb = *(const float2*)(sB + ((ks << 4) + (wn << 2) + j) * BW + (lane << 1));
                bfr[j][0] = __float_as_uint(vb.x); bfr[j][1] = __float_as_uint(vb.y);
            }
            #pragma unroll
            for (int i = 0; i < 4; i++)
                #pragma unroll
                for (int j = 0; j < 4; j++)
                    mma_tf32(acc[i][j], afr[i], bfr[j]);
        }

        if (c + 1 < nch) stores(smem + (cur ^ 1) * BUF_W);
        __syncthreads();
    }

    int g = lane >> 2, t = lane & 3;
    int m0 = bm * 128 + wm * 64;
    int n0 = bn * 128 + wn * 32;
    #pragma unroll
    for (int i = 0; i < 4; i++) {
        int row0 = m0 + i * 16 + g;
        #pragma unroll
        for (int j = 0; j < 4; j++) {
            int col = n0 + j * 8 + t * 2;
            float2 bb = *(const float2*)(bias + col);
            float2 v0, v1;
            v0.x = acc[i][j][0] + bb.x; v0.y = acc[i][j][1] + bb.y;
            v1.x = acc[i][j][2] + bb.x; v1.y = acc[i][j][3] + bb.y;
            if (epi == 1) {
                float2 r0 = *(const float2*)(res + (size_t)row0 * N + col);
                float2 r1 = *(const float2*)(res + (size_t)(row0 + 8) * N + col);
                v0.x += r0.x; v0.y += r0.y;
                v1.x += r1.x; v1.y += r1.y;
            } else if (epi == 2) {
                v0.x = gelu_exact(v0.x); v0.y = gelu_exact(v0.y);
                v1.x = gelu_exact(v1.x); v1.y = gelu_exact(v1.y);
            }
            *(float2*)(C + (size_t)row0 * N + col)       = v0;
            *(float2*)(C + (size_t)(row0 + 8) * N + col) = v1;
        }
    }
}

// =============== TF32 mma.sync flash attention ===============
// grid (SEQ/128, NH, BATCH), 256 threads (8 warps).
// Warp w owns q rows [w*16, w*16+16): full softmax row stats stay in-warp.
// K/V tiles (64kv x 64d) staged in fragment-ordered smem; frag(kvoct,doct)
// at (kvoct*8+doct)*68 words. P staged per-warp in A-frag order (8 frags x 132).
#define KVF_W 4352                 // 64 frags * 68
#define PF_W  (8*132)              // per warp
#define ATT_SMEM ((2*KVF_W + 8*PF_W)*4)   // 68608 bytes

__global__ void __launch_bounds__(256)
attn_kernel(const float* __restrict__ qkv, const int* __restrict__ mask,
            float* __restrict__ out)
{
    extern __shared__ float sm[];
    float* Ksm = sm;
    float* Vsm = sm + KVF_W;
    float* Pw  = sm + 2 * KVF_W + (threadIdx.x >> 5) * PF_W;

    int qb = blockIdx.x, h = blockIdx.y, b = blockIdx.z;
    int tid = threadIdx.x, w = tid >> 5, lane = tid & 31;
    int g = lane >> 2, t = lane & 3;

    // Q fragments in registers (scale folded, tf32)
    uint32_t qf[8][4];
    {
        const float* q0 = qkv + (size_t)(b * SEQ + qb * 128 + w * 16 + g) * QKVW + h * HD;
        const float* q8 = q0 + (size_t)8 * QKVW;
        #pragma unroll
        for (int ks = 0; ks < 8; ks++) {
            qf[ks][0] = f2tf32(q0[ks * 8 + t]     * ATT_SCALE);
            qf[ks][1] = f2tf32(q8[ks * 8 + t]     * ATT_SCALE);
            qf[ks][2] = f2tf32(q0[ks * 8 + t + 4] * ATT_SCALE);
            qf[ks][3] = f2tf32(q8[ks * 8 + t + 4] * ATT_SCALE);
        }
    }

    float o[8][4];
    #pragma unroll
    for (int nt = 0; nt < 8; nt++)
        #pragma unroll
        for (int r = 0; r < 4; r++) o[nt][r] = 0.f;
    float m0 = -1e30f, m1 = -1e30f, l0 = 0.f, l1 = 0.f;

    const int* maskb = mask + (size_t)b * SEQ * SEQ;
    int qi0 = qb * 128 + w * 16 + g;

    for (int kvb = 0; kvb < SEQ / 64; kvb++) {
        __syncthreads();   // prior iter's K/V reads complete
        const float* kbase = qkv + (size_t)(b * SEQ + kvb * 64) * QKVW + DIMM + h * HD;
        const float* vbase = kbase + DIMM;
        #pragma unroll
        for (int i = 0; i < 4; i++) {
            int idx = tid + i * 256;
            int kv = idx >> 4, d4 = (idx & 15) << 2;
            int fo = ((kv >> 3) * 8 + (d4 >> 3)) * 68;
            float4 kval = *(const float4*)(kbase + (size_t)kv * QKVW + d4);
            float* kp = Ksm + fo + ((kv & 7) << 3) + ((d4 >> 2) & 1);
            kp[0] = tfv(kval.x); kp[2] = tfv(kval.y);
            kp[4] = tfv(kval.z); kp[6] = tfv(kval.w);
            float4 vval = *(const float4*)(vbase + (size_t)kv * QKVW + d4);
            float* vp = Vsm + fo + (((((d4 & 7) << 2) | (kv & 3))) << 1) + ((kv >> 2) & 1);
            vp[0] = tfv(vval.x); vp[8] = tfv(vval.y);
            vp[16] = tfv(vval.z); vp[24] = tfv(vval.w);
        }
        __syncthreads();

        // S = Q K^T  (warp: m16 x n64, k64)
        float s[8][4];
        #pragma unroll
        for (int nt = 0; nt < 8; nt++)
            #pragma unroll
            for (int r = 0; r < 4; r++) s[nt][r] = 0.f;
        #pragma unroll
        for (int ks = 0; ks < 8; ks++) {
            #pragma unroll
            for (int nt = 0; nt < 8; nt++) {
                float2 bvv = *(const float2*)(Ksm + (nt * 8 + ks) * 68 + lane * 2);
                uint32_t bf[2] = { __float_as_uint(bvv.x), __float_as_uint(bvv.y) };
                mma_tf32(s[nt], qf[ks], bf);
            }
        }

        // mask + online softmax (rows g and g+8, cols nt*8 + 2t, 2t+1)
        int kj0 = kvb * 64;
        float rmax0 = -1e30f, rmax1 = -1e30f;
        #pragma unroll
        for (int nt = 0; nt < 8; nt++) {
            int col = kj0 + nt * 8 + 2 * t;
            int2 mv0 = *(const int2*)(maskb + (size_t)qi0 * SEQ + col);
            int2 mv1 = *(const int2*)(maskb + (size_t)(qi0 + 8) * SEQ + col);
            if (mv0.x == 0) s[nt][0] = -10000.f;
            if (mv0.y == 0) s[nt][1] = -10000.f;
            if (mv1.x == 0) s[nt][2] = -10000.f;
            if (mv1.y == 0) s[nt][3] = -10000.f;
            rmax0 = fmaxf(rmax0, fmaxf(s[nt][0], s[nt][1]));
            rmax1 = fmaxf(rmax1, fmaxf(s[nt][2], s[nt][3]));
        }
        rmax0 = fmaxf(rmax0, __shfl_xor_sync(0xffffffffu, rmax0, 1));
        rmax0 = fmaxf(rmax0, __shfl_xor_sync(0xffffffffu, rmax0, 2));
        rmax1 = fmaxf(rmax1, __shfl_xor_sync(0xffffffffu, rmax1, 1));
        rmax1 = fmaxf(rmax1, __shfl_xor_sync(0xffffffffu, rmax1, 2));
        float mn0 = fmaxf(m0, rmax0), mn1 = fmaxf(m1, rmax1);
        float c0 = __expf(m0 - mn0), c1 = __expf(m1 - mn1);
        m0 = mn0; m1 = mn1;
        float ps0 = 0.f, ps1 = 0.f;
        int k0i = 2 * t, k1i = 2 * t + 1;
        int la = g << 2;
        int w0 = ((la | (k0i & 3)) << 2) + ((k0i >> 2) << 1);
        int w1 = ((la | (k1i & 3)) << 2) + ((k1i >> 2) << 1);
        #pragma unroll
        for (int nt = 0; nt < 8; nt++) {
            float p0 = __expf(s[nt][0] - mn0);
            float p1 = __expf(s[nt][1] - mn0);
            float p2 = __expf(s[nt][2] - mn1);
            float p3 = __expf(s[nt][3] - mn1);
            ps0 += p0 + p1; ps1 += p2 + p3;
            o[nt][0] *= c0; o[nt][1] *= c0;
            o[nt][2] *= c1; o[nt][3] *= c1;
            float* pb = Pw + nt * 132;
            pb[w0]     = tfv(p0);
            pb[w1]     = tfv(p1);
            pb[w0 + 1] = tfv(p2);
            pb[w1 + 1] = tfv(p3);
        }
        l0 = l0 * c0 + ps0;
        l1 = l1 * c1 + ps1;
        __syncwarp();   // P visible within warp

        // O += P V  (A frags from per-warp P, B frags from V)
        #pragma unroll
        for (int ks = 0; ks < 8; ks++) {
            float4 pa = *(const float4*)(Pw + ks * 132 + lane * 4);
            uint32_t af[4] = { __float_as_uint(pa.x), __float_as_uint(pa.y),
                               __float_as_uint(pa.z), __float_as_uint(pa.w) };
            #pragma unroll
            for (int nt = 0; nt < 8; nt++) {
                float2 vb = *(const float2*)(Vsm + (ks * 8 + nt) * 68 + lane * 2);
                uint32_t bf[2] = { __float_as_uint(vb.x), __float_as_uint(vb.y) };
                mma_tf32(o[nt], af, bf);
            }
        }
    }

    l0 += __shfl_xor_sync(0xffffffffu, l0, 1);
    l0 += __shfl_xor_sync(0xffffffffu, l0, 2);
    l1 += __shfl_xor_sync(0xffffffffu, l1, 1);
    l1 += __shfl_xor_sync(0xffffffffu, l1, 2);
    float inv0 = 1.0f / l0, inv1 = 1.0f / l1;

    float* ob  = out + (size_t)(b * SEQ + qb * 128 + w * 16 + g) * DIMM + h * HD;
    float* ob8 = ob + (size_t)8 * DIMM;
    #pragma unroll
    for (int nt = 0; nt < 8; nt++) {
        int col = nt * 8 + 2 * t;
        *(float2*)(ob + col)  = make_float2(o[nt][0] * inv0, o[nt][1] * inv0);
        *(float2*)(ob8 + col) = make_float2(o[nt][2] * inv1, o[nt][3] * inv1);
    }
}

// ---------------- launch ----------------
extern "C" void kernel_launch(void* const* d_in, const int* in_sizes, int n_in,
                              void* d_out, int out_size)
{
    const float* x      = (const float*)d_in[0];
    const int*   mask   = (const int*)  d_in[1];
    const float* w_qkv  = (const float*)d_in[2];
    const float* b_qkv  = (const float*)d_in[3];
    const float* w_proj = (const float*)d_in[4];
    const float* b_proj = (const float*)d_in[5];
    const float* g1     = (const float*)d_in[6];
    const float* beta1  = (const float*)d_in[7];
    const float* g2     = (const float*)d_in[8];
    const float* beta2  = (const float*)d_in[9];
    const float* w1     = (const float*)d_in[10];
    const float* b1     = (const float*)d_in[11];
    const float* w2     = (const float*)d_in[12];
    const float* b2     = (const float*)d_in[13];
    float* out = (float*)d_out;

    float *p_h, *p_qkv, *p_wa, *p_x1, *p_hid;
    cudaGetSymbolAddress((void**)&p_h,   g_h);
    cudaGetSymbolAddress((void**)&p_qkv, g_qkv);
    cudaGetSymbolAddress((void**)&p_wa,  g_wa);
    cudaGetSymbolAddress((void**)&p_x1,  g_x1);
    cudaGetSymbolAddress((void**)&p_hid, g_hid);

    cudaFuncSetAttribute(tgemm_kernel,
                         cudaFuncAttributeMaxDynamicSharedMemorySize, GSMEM_BYTES);
    cudaFuncSetAttribute(attn_kernel,
                         cudaFuncAttributeMaxDynamicSharedMemorySize, ATT_SMEM);

    // LN1
    ln_kernel<<<TOK, 256>>>(x, g1, beta1, p_h);
    // qkv = h @ w_qkv + b_qkv           [8192,768] x [768,2304]
    tgemm_kernel<<<dim3(QKVW / 128, TOK / 128), 256, GSMEM_BYTES>>>(
        p_h, w_qkv, b_qkv, nullptr, p_qkv, DIMM, QKVW, 0);
    // attention (tf32 mma)
    attn_kernel<<<dim3(SEQ / 128, NH, BATCH), 256, ATT_SMEM>>>(p_qkv, mask, p_wa);
    // x1 = x + wa @ w_proj + b_proj     [8192,768] x [768,768]
    tgemm_kernel<<<dim3(DIMM / 128, TOK / 128), 256, GSMEM_BYTES>>>(
        p_wa, w_proj, b_proj, x, p_x1, DIMM, DIMM, 1);
    // LN2
    ln_kernel<<<TOK, 256>>>(p_x1, g2, beta2, p_h);
    // hid = gelu(h @ w1 + b1)           [8192,768] x [768,3072]
    tgemm_kernel<<<dim3(HIDDEN / 128, TOK / 128), 256, GSMEM_BYTES>>>(
        p_h, w1, b1, nullptr, p_hid, DIMM, HIDDEN, 2);
    // out = x1 + hid @ w2 + b2          [8192,3072] x [3072,768]
    tgemm_kernel<<<dim3(DIMM / 128, TOK / 128), 256, GSMEM_BYTES>>>(
        p_hid, w2, b2, p_x1, out, HIDDEN, DIMM, 1);
}

// round 16
// speedup vs baseline: 3.0434x; 1.2081x over previous
#include <cuda_runtime.h>
#include <math.h>
#include <stdint.h>

#define DIMM 768
#define NH 12
#define HD 64
#define HIDDEN 3072
#define BATCH 4
#define SEQ 2048
#define TOK (BATCH*SEQ)
#define QKVW (3*DIMM)
#define EPS 1e-6f
#define ATT_SCALE 0.125f   // 64^-0.5

// ---------------- scratch (no cudaMalloc allowed) ----------------
// Fragment-ordered tf32 operand buffers (A'-layout / B'-layout):
//   A'[bm][c][fa][128]: fa = mt*4+ks (mt=(r&127)>>4, ks=(k&31)>>3)
//     word = lane*4+reg, lane=((r&7)<<2)|(k&3), reg=((r>>3)&1)|(((k>>2)&1)<<1)
//   B'[bn][c][fb][64]:  fb = ks*16+nt (nt=(n&127)>>3)
//     word = lane*2+reg, lane=((n&7)<<2)|(k&3), reg=(k>>2)&1
// Each 128x32 chunk of A' and B' is a contiguous 4096-word (16KB) block.
__device__ float g_hf[TOK*DIMM];        // LN output, A'-frag layout
__device__ float g_qkv[TOK*QKVW];       // qkv projection (normal layout)
__device__ float g_waf[TOK*DIMM];       // attention output, A'-frag layout
__device__ float g_x1[TOK*DIMM];        // x after attention residual (normal)
__device__ float g_hidf[TOK*HIDDEN];    // FFN hidden, A'-frag layout
__device__ float g_wqkvf[DIMM*QKVW];    // weights, B'-frag layout
__device__ float g_wprojf[DIMM*DIMM];
__device__ float g_w1f[DIMM*HIDDEN];
__device__ float g_w2f[HIDDEN*DIMM];

__device__ __forceinline__ uint32_t f2tf32(float x) {
    uint32_t u;
    asm("cvt.rna.tf32.f32 %0, %1;" : "=r"(u) : "f"(x));
    return u;
}
__device__ __forceinline__ float tfv(float x) {
    return __uint_as_float(f2tf32(x));
}
__device__ __forceinline__ uint32_t smem_u32(const void* p) {
    uint32_t a;
    asm("{ .reg .u64 t; cvta.to.shared.u64 t, %1; cvt.u32.u64 %0, t; }"
        : "=r"(a) : "l"(p));
    return a;
}
__device__ __forceinline__ void cpa16(uint32_t saddr, const float* g) {
    asm volatile("cp.async.cg.shared.global [%0], [%1], 16;"
                 :: "r"(saddr), "l"(__cvta_generic_to_global(g)) : "memory");
}
#define CPA_COMMIT() asm volatile("cp.async.commit_group;" ::: "memory")
#define CPA_WAIT1()  asm volatile("cp.async.wait_group 1;"  ::: "memory")

__device__ __forceinline__ void mma_tf32(float* d, const uint32_t* a, const uint32_t* b) {
    asm volatile(
        "mma.sync.aligned.m16n8k8.row.col.f32.tf32.tf32.f32 "
        "{%0,%1,%2,%3}, {%4,%5,%6,%7}, {%8,%9}, {%0,%1,%2,%3};"
        : "+f"(d[0]), "+f"(d[1]), "+f"(d[2]), "+f"(d[3])
        : "r"(a[0]), "r"(a[1]), "r"(a[2]), "r"(a[3]), "r"(b[0]), "r"(b[1]));
}

__device__ __forceinline__ float gelu_exact(float x) {
    return 0.5f * x * (1.0f + erff(x * 0.70710678118654752f));
}

// ---------------- weight transform: w[K][N] -> B'-frag tf32 ----------------
__global__ void wtrans_kernel(const float* __restrict__ w, float* __restrict__ Bf,
                              int K, int N)
{
    int idx = blockIdx.x * 256 + threadIdx.x;        // output word index
    int word = idx & 63;
    int lane = word >> 1, reg = word & 1;
    int fb = (idx >> 6) & 63;
    int ks = fb >> 4, nt = fb & 15;
    int rest = idx >> 12;
    int nch = K >> 5;
    int c = rest % nch, bn = rest / nch;
    int n = bn * 128 + nt * 8 + (lane >> 2);
    int k = c * 32 + ks * 8 + (reg << 2) + (lane & 3);
    Bf[idx] = tfv(w[(size_t)k * N + n]);
}

// ---------------- LayerNorm -> A'-frag tf32 output ----------------
__global__ void ln_kernel(const float* __restrict__ x,
                          const float* __restrict__ gamma,
                          const float* __restrict__ beta,
                          float* __restrict__ outf)
{
    int row = blockIdx.x;
    const float* xr = x + (size_t)row * DIMM;
    int t = threadIdx.x;
    float v0 = xr[t], v1 = xr[t + 256], v2 = xr[t + 512];
    float s  = v0 + v1 + v2;
    float sq = v0*v0 + v1*v1 + v2*v2;
    #pragma unroll
    for (int o = 16; o > 0; o >>= 1) {
        s  += __shfl_xor_sync(0xffffffffu, s,  o);
        sq += __shfl_xor_sync(0xffffffffu, sq, o);
    }
    __shared__ float rs[8], rq[8];
    int w = t >> 5, l = t & 31;
    if (l == 0) { rs[w] = s; rq[w] = sq; }
    __syncthreads();
    s = 0.f; sq = 0.f;
    #pragma unroll
    for (int i = 0; i < 8; i++) { s += rs[i]; sq += rq[i]; }
    float mu  = s * (1.0f / DIMM);
    float var = sq * (1.0f / DIMM) - mu * mu;
    float r   = rsqrtf(var + EPS);

    int bm = row >> 7, mt = (row & 127) >> 4;
    int lane_r = (row & 7) << 2, regb0 = (row >> 3) & 1;
    #pragma unroll
    for (int e = 0; e < 3; e++) {
        int k = t + e * 256;
        float v = (e == 0 ? v0 : (e == 1 ? v1 : v2));
        float val = (v - mu) * r * gamma[k] + beta[k];
        int cc = k >> 5, ks = (k >> 3) & 3;
        int fa = mt * 4 + ks;
        int lane = lane_r | (k & 3);
        int reg = regb0 | (((k >> 2) & 1) << 1);
        outf[(((size_t)bm * 24 + cc) * 32 + fa) * 128 + lane * 4 + reg] = tfv(val);
    }
}

// =================== TF32 mma.sync GEMM v2 (cp.async + pre-formatted frags) ===================
// A' frag global, B' frag global. 128x128 CTA tile, 8 warps (2m x 4n), warp 64x32.
// 32-K chunks, 3-stage cp.async ring (32KB/stage).
#define STAGE_W 8192
#define NSTAGE 3
#define GSMEM_BYTES (NSTAGE*STAGE_W*4)   // 98304

// epi: 0 = bias, 1 = bias+res, 2 = bias+gelu (normal out), 3 = bias+gelu -> A'-frag out
__global__ void __launch_bounds__(256, 2)
tgemm_kernel(const float* __restrict__ Af, const float* __restrict__ Bf,
             const float* __restrict__ bias, const float* __restrict__ res,
             float* __restrict__ C, int K, int N, int epi)
{
    extern __shared__ float smem[];
    uint32_t sbase = smem_u32(smem);
    int tid = threadIdx.x;
    int bm = blockIdx.y, bn = blockIdx.x;
    int w = tid >> 5, lane = tid & 31;
    int wm = w >> 2, wn = w & 3;
    int nch = K >> 5;

    float acc[4][4][4];
    #pragma unroll
    for (int i = 0; i < 4; i++)
        #pragma unroll
        for (int j = 0; j < 4; j++)
            #pragma unroll
            for (int r = 0; r < 4; r++) acc[i][j][r] = 0.f;

    const float* Abase = Af + ((size_t)bm * nch << 12);
    const float* Bbase = Bf + ((size_t)bn * nch << 12);

    auto issue = [&](int c) {
        const float* a = Abase + ((size_t)c << 12);
        const float* b = Bbase + ((size_t)c << 12);
        uint32_t st = sbase + (uint32_t)(c % NSTAGE) * (STAGE_W * 4);
        #pragma unroll
        for (int i = 0; i < 4; i++)
            cpa16(st + (tid * 4 + i * 1024) * 4, a + tid * 4 + i * 1024);
        #pragma unroll
        for (int i = 0; i < 4; i++)
            cpa16(st + (4096 + tid * 4 + i * 1024) * 4, b + tid * 4 + i * 1024);
    };

    issue(0); CPA_COMMIT();
    issue(1); CPA_COMMIT();

    for (int c = 0; c < nch; c++) {
        CPA_WAIT1();
        __syncthreads();
        if (c + 2 < nch) issue(c + 2);
        CPA_COMMIT();

        const float* st = smem + (c % NSTAGE) * STAGE_W;
        const float* sB = st + 4096;
        #pragma unroll
        for (int ks = 0; ks < 4; ks++) {
            uint32_t afr[4][4], bfr[4][2];
            #pragma unroll
            for (int i = 0; i < 4; i++) {
                float4 va = *(const float4*)(st + (((wm << 2) + i) * 4 + ks) * 128 + (lane << 2));
                afr[i][0] = __float_as_uint(va.x); afr[i][1] = __float_as_uint(va.y);
                afr[i][2] = __float_as_uint(va.z); afr[i][3] = __float_as_uint(va.w);
            }
            #pragma unroll
            for (int j = 0; j < 4; j++) {
                float2 vb = *(const float2*)(sB + ((ks << 4) + (wn << 2) + j) * 64 + (lane << 1));
                bfr[j][0] = __float_as_uint(vb.x); bfr[j][1] = __float_as_uint(vb.y);
            }
            #pragma unroll
            for (int i = 0; i < 4; i++)
                #pragma unroll
                for (int j = 0; j < 4; j++)
                    mma_tf32(acc[i][j], afr[i], bfr[j]);
        }
    }

    // ---- epilogue ----
    int g = lane >> 2, t = lane & 3;
    int m0 = bm * 128 + wm * 64;
    int n0 = bn * 128 + wn * 32;
    int nchO = N >> 5;
    #pragma unroll
    for (int i = 0; i < 4; i++) {
        int row0 = m0 + i * 16 + g;
        #pragma unroll
        for (int j = 0; j < 4; j++) {
            int col = n0 + j * 8 + t * 2;
            float2 bb = *(const float2*)(bias + col);
            float2 v0, v1;
            v0.x = acc[i][j][0] + bb.x; v0.y = acc[i][j][1] + bb.y;
            v1.x = acc[i][j][2] + bb.x; v1.y = acc[i][j][3] + bb.y;
            if (epi == 1) {
                float2 r0 = *(const float2*)(res + (size_t)row0 * N + col);
                float2 r1 = *(const float2*)(res + (size_t)(row0 + 8) * N + col);
                v0.x += r0.x; v0.y += r0.y;
                v1.x += r1.x; v1.y += r1.y;
            } else if (epi >= 2) {
                v0.x = gelu_exact(v0.x); v0.y = gelu_exact(v0.y);
                v1.x = gelu_exact(v1.x); v1.y = gelu_exact(v1.y);
            }
            if (epi == 3) {
                // A'-frag tf32 store (consumed by next GEMM)
                int cc = col >> 5, ks = (col >> 3) & 3;
                int fa = ((wm << 2) + i) * 4 + ks;
                size_t idx = (((size_t)bm * nchO + cc) * 32 + fa) * 128
                           + (size_t)(((g << 2) | (col & 3)) * 4 + (((t >> 1) & 1) << 1));
                C[idx]     = tfv(v0.x);
                C[idx + 4] = tfv(v0.y);
                C[idx + 1] = tfv(v1.x);
                C[idx + 5] = tfv(v1.y);
            } else {
                *(float2*)(C + (size_t)row0 * N + col)       = v0;
                *(float2*)(C + (size_t)(row0 + 8) * N + col) = v1;
            }
        }
    }
}

// =============== TF32 mma.sync flash attention (A'-frag output) ===============
#define KVF_W 4352                 // 64 frags * 68
#define PF_W  (8*132)              // per warp
#define ATT_SMEM ((2*KVF_W + 8*PF_W)*4)   // 68608 bytes

__global__ void __launch_bounds__(256)
attn_kernel(const float* __restrict__ qkv, const int* __restrict__ mask,
            float* __restrict__ outf)
{
    extern __shared__ float sm[];
    float* Ksm = sm;
    float* Vsm = sm + KVF_W;
    float* Pw  = sm + 2 * KVF_W + (threadIdx.x >> 5) * PF_W;

    int qb = blockIdx.x, h = blockIdx.y, b = blockIdx.z;
    int tid = threadIdx.x, w = tid >> 5, lane = tid & 31;
    int g = lane >> 2, t = lane & 3;

    uint32_t qf[8][4];
    {
        const float* q0 = qkv + (size_t)(b * SEQ + qb * 128 + w * 16 + g) * QKVW + h * HD;
        const float* q8 = q0 + (size_t)8 * QKVW;
        #pragma unroll
        for (int ks = 0; ks < 8; ks++) {
            qf[ks][0] = f2tf32(q0[ks * 8 + t]     * ATT_SCALE);
            qf[ks][1] = f2tf32(q8[ks * 8 + t]     * ATT_SCALE);
            qf[ks][2] = f2tf32(q0[ks * 8 + t + 4] * ATT_SCALE);
            qf[ks][3] = f2tf32(q8[ks * 8 + t + 4] * ATT_SCALE);
        }
    }

    float o[8][4];
    #pragma unroll
    for (int nt = 0; nt < 8; nt++)
        #pragma unroll
        for (int r = 0; r < 4; r++) o[nt][r] = 0.f;
    float m0 = -1e30f, m1 = -1e30f, l0 = 0.f, l1 = 0.f;

    const int* maskb = mask + (size_t)b * SEQ * SEQ;
    int qi0 = qb * 128 + w * 16 + g;

    for (int kvb = 0; kvb < SEQ / 64; kvb++) {
        __syncthreads();
        const float* kbase = qkv + (size_t)(b * SEQ + kvb * 64) * QKVW + DIMM + h * HD;
        const float* vbase = kbase + DIMM;
        #pragma unroll
        for (int i = 0; i < 4; i++) {
            int idx = tid + i * 256;
            int kv = idx >> 4, d4 = (idx & 15) << 2;
            int fo = ((kv >> 3) * 8 + (d4 >> 3)) * 68;
            float4 kval = *(const float4*)(kbase + (size_t)kv * QKVW + d4);
            float* kp = Ksm + fo + ((kv & 7) << 3) + ((d4 >> 2) & 1);
            kp[0] = tfv(kval.x); kp[2] = tfv(kval.y);
            kp[4] = tfv(kval.z); kp[6] = tfv(kval.w);
            float4 vval = *(const float4*)(vbase + (size_t)kv * QKVW + d4);
            float* vp = Vsm + fo + (((((d4 & 7) << 2) | (kv & 3))) << 1) + ((kv >> 2) & 1);
            vp[0] = tfv(vval.x); vp[8] = tfv(vval.y);
            vp[16] = tfv(vval.z); vp[24] = tfv(vval.w);
        }
        __syncthreads();

        float s[8][4];
        #pragma unroll
        for (int nt = 0; nt < 8; nt++)
            #pragma unroll
            for (int r = 0; r < 4; r++) s[nt][r] = 0.f;
        #pragma unroll
        for (int ks = 0; ks < 8; ks++) {
            #pragma unroll
            for (int nt = 0; nt < 8; nt++) {
                float2 bvv = *(const float2*)(Ksm + (nt * 8 + ks) * 68 + lane * 2);
                uint32_t bf[2] = { __float_as_uint(bvv.x), __float_as_uint(bvv.y) };
                mma_tf32(s[nt], qf[ks], bf);
            }
        }

        int kj0 = kvb * 64;
        float rmax0 = -1e30f, rmax1 = -1e30f;
        #pragma unroll
        for (int nt = 0; nt < 8; nt++) {
            int col = kj0 + nt * 8 + 2 * t;
            int2 mv0 = *(const int2*)(maskb + (size_t)qi0 * SEQ + col);
            int2 mv1 = *(const int2*)(maskb + (size_t)(qi0 + 8) * SEQ + col);
            if (mv0.x == 0) s[nt][0] = -10000.f;
            if (mv0.y == 0) s[nt][1] = -10000.f;
            if (mv1.x == 0) s[nt][2] = -10000.f;
            if (mv1.y == 0) s[nt][3] = -10000.f;
            rmax0 = fmaxf(rmax0, fmaxf(s[nt][0], s[nt][1]));
            rmax1 = fmaxf(rmax1, fmaxf(s[nt][2], s[nt][3]));
        }
        rmax0 = fmaxf(rmax0, __shfl_xor_sync(0xffffffffu, rmax0, 1));
        rmax0 = fmaxf(rmax0, __shfl_xor_sync(0xffffffffu, rmax0, 2));
        rmax1 = fmaxf(rmax1, __shfl_xor_sync(0xffffffffu, rmax1, 1));
        rmax1 = fmaxf(rmax1, __shfl_xor_sync(0xffffffffu, rmax1, 2));
        float mn0 = fmaxf(m0, rmax0), mn1 = fmaxf(m1, rmax1);
        float c0 = __expf(m0 - mn0), c1 = __expf(m1 - mn1);
        m0 = mn0; m1 = mn1;
        float ps0 = 0.f, ps1 = 0.f;
        int k0i = 2 * t, k1i = 2 * t + 1;
        int la = g << 2;
        int w0 = ((la | (k0i & 3)) << 2) + ((k0i >> 2) << 1);
        int w1 = ((la | (k1i & 3)) << 2) + ((k1i >> 2) << 1);
        #pragma unroll
        for (int nt = 0; nt < 8; nt++) {
            float p0 = __expf(s[nt][0] - mn0);
            float p1 = __expf(s[nt][1] - mn0);
            float p2 = __expf(s[nt][2] - mn1);
            float p3 = __expf(s[nt][3] - mn1);
            ps0 += p0 + p1; ps1 += p2 + p3;
            o[nt][0] *= c0; o[nt][1] *= c0;
            o[nt][2] *= c1; o[nt][3] *= c1;
            float* pb = Pw + nt * 132;
            pb[w0]     = tfv(p0);
            pb[w1]     = tfv(p1);
            pb[w0 + 1] = tfv(p2);
            pb[w1 + 1] = tfv(p3);
        }
        l0 = l0 * c0 + ps0;
        l1 = l1 * c1 + ps1;
        __syncwarp();

        #pragma unroll
        for (int ks = 0; ks < 8; ks++) {
            float4 pa = *(const float4*)(Pw + ks * 132 + lane * 4);
            uint32_t af[4] = { __float_as_uint(pa.x), __float_as_uint(pa.y),
                               __float_as_uint(pa.z), __float_as_uint(pa.w) };
            #pragma unroll
            for (int nt = 0; nt < 8; nt++) {
                float2 vb = *(const float2*)(Vsm + (ks * 8 + nt) * 68 + lane * 2);
                uint32_t bf[2] = { __float_as_uint(vb.x), __float_as_uint(vb.y) };
                mma_tf32(o[nt], af, bf);
            }
        }
    }

    l0 += __shfl_xor_sync(0xffffffffu, l0, 1);
    l0 += __shfl_xor_sync(0xffffffffu, l0, 2);
    l1 += __shfl_xor_sync(0xffffffffu, l1, 1);
    l1 += __shfl_xor_sync(0xffffffffu, l1, 2);
    float inv0 = 1.0f / l0, inv1 = 1.0f / l1;

    // A'-frag tf32 output (consumed by proj GEMM)
    int r0g = b * SEQ + qb * 128 + w * 16 + g;
    int bmA = r0g >> 7;
    int lane_r = g << 2;
    int regb = ((t >> 1) & 1) << 1;
    #pragma unroll
    for (int nt = 0; nt < 8; nt++) {
        int col = h * HD + nt * 8 + 2 * t;
        int cc = col >> 5, ks = (col >> 3) & 3;
        int fa = w * 4 + ks;
        size_t idx = (((size_t)bmA * 24 + cc) * 32 + fa) * 128
                   + (size_t)((lane_r | (col & 3)) * 4 + regb);
        outf[idx]     = tfv(o[nt][0] * inv0);
        outf[idx + 4] = tfv(o[nt][1] * inv0);
        outf[idx + 1] = tfv(o[nt][2] * inv1);
        outf[idx + 5] = tfv(o[nt][3] * inv1);
    }
}

// ---------------- launch ----------------
extern "C" void kernel_launch(void* const* d_in, const int* in_sizes, int n_in,
                              void* d_out, int out_size)
{
    const float* x      = (const float*)d_in[0];
    const int*   mask   = (const int*)  d_in[1];
    const float* w_qkv  = (const float*)d_in[2];
    const float* b_qkv  = (const float*)d_in[3];
    const float* w_proj = (const float*)d_in[4];
    const float* b_proj = (const float*)d_in[5];
    const float* g1     = (const float*)d_in[6];
    const float* beta1  = (const float*)d_in[7];
    const float* g2     = (const float*)d_in[8];
    const float* beta2  = (const float*)d_in[9];
    const float* w1     = (const float*)d_in[10];
    const float* b1     = (const float*)d_in[11];
    const float* w2     = (const float*)d_in[12];
    const float* b2     = (const float*)d_in[13];
    float* out = (float*)d_out;

    float *p_hf, *p_qkv, *p_waf, *p_x1, *p_hidf;
    float *p_wqkvf, *p_wprojf, *p_w1f, *p_w2f;
    cudaGetSymbolAddress((void**)&p_hf,     g_hf);
    cudaGetSymbolAddress((void**)&p_qkv,    g_qkv);
    cudaGetSymbolAddress((void**)&p_waf,    g_waf);
    cudaGetSymbolAddress((void**)&p_x1,     g_x1);
    cudaGetSymbolAddress((void**)&p_hidf,   g_hidf);
    cudaGetSymbolAddress((void**)&p_wqkvf,  g_wqkvf);
    cudaGetSymbolAddress((void**)&p_wprojf, g_wprojf);
    cudaGetSymbolAddress((void**)&p_w1f,    g_w1f);
    cudaGetSymbolAddress((void**)&p_w2f,    g_w2f);

    cudaFuncSetAttribute(tgemm_kernel,
                         cudaFuncAttributeMaxDynamicSharedMemorySize, GSMEM_BYTES);
    cudaFuncSetAttribute(attn_kernel,
                         cudaFuncAttributeMaxDynamicSharedMemorySize, ATT_SMEM);

    // weight transforms (frag-ordered tf32)
    wtrans_kernel<<<DIMM*QKVW/256, 256>>>(w_qkv,  p_wqkvf,  DIMM,   QKVW);
    wtrans_kernel<<<DIMM*DIMM/256, 256>>>(w_proj, p_wprojf, DIMM,   DIMM);
    wtrans_kernel<<<DIMM*HIDDEN/256, 256>>>(w1,   p_w1f,    DIMM,   HIDDEN);
    wtrans_kernel<<<HIDDEN*DIMM/256, 256>>>(w2,   p_w2f,    HIDDEN, DIMM);

    // LN1 -> frag
    ln_kernel<<<TOK, 256>>>(x, g1, beta1, p_hf);
    // qkv = h @ w_qkv + b_qkv           [8192,768] x [768,2304] (normal out)
    tgemm_kernel<<<dim3(QKVW / 128, TOK / 128), 256, GSMEM_BYTES>>>(
        p_hf, p_wqkvf, b_qkv, nullptr, p_qkv, DIMM, QKVW, 0);
    // attention -> frag out
    attn_kernel<<<dim3(SEQ / 128, NH, BATCH), 256, ATT_SMEM>>>(p_qkv, mask, p_waf);
    // x1 = x + wa @ w_proj + b_proj     [8192,768] x [768,768] (normal out)
    tgemm_kernel<<<dim3(DIMM / 128, TOK / 128), 256, GSMEM_BYTES>>>(
        p_waf, p_wprojf, b_proj, x, p_x1, DIMM, DIMM, 1);
    // LN2 -> frag
    ln_kernel<<<TOK, 256>>>(p_x1, g2, beta2, p_hf);
    // hid = gelu(h @ w1 + b1)           [8192,768] x [768,3072] (frag out)
    tgemm_kernel<<<dim3(HIDDEN / 128, TOK / 128), 256, GSMEM_BYTES>>>(
        p_hf, p_w1f, b1, nullptr, p_hidf, DIMM, HIDDEN, 3);
    // out = x1 + hid @ w2 + b2          [8192,3072] x [3072,768] (normal out)
    tgemm_kernel<<<dim3(DIMM / 128, TOK / 128), 256, GSMEM_BYTES>>>(
        p_hidf, p_w2f, b2, p_x1, out, HIDDEN, DIMM, 1);
}